// round 1
// baseline (speedup 1.0000x reference)
#include <cuda_runtime.h>
#include <cstdint>
#include <math.h>

// Problem constants
#define S_LEN 128
#define B_SZ  128
#define E_DIM 64
#define H_DIM 8
#define NQG   8     // qubits per gate-block in LSTM cell
#define T_OUT 12
#define NROWS (S_LEN * B_SZ)
#define N_OPS 30

// ---------------------------------------------------------------------------
// Device scratch (no allocations allowed)
// ---------------------------------------------------------------------------
__device__ int   g_is64;                 // 1 if sentence is int64, 0 if int32
__device__ float g_zx[NROWS * 32];       // x-part of z (+ b_in + phi), per (s,b,g*8+q)
__device__ float g_h[NROWS * H_DIM];     // hidden states outs[s][b][h]

struct QOp { int type; int a; int b; float c; float s; }; // type 0=rx,1=ry,2=rz,3=cnot
struct QOpsParam { QOp ops[N_OPS]; };

// ---------------------------------------------------------------------------
// Kernel 0: detect int32 vs int64 sentence encoding.
// If values are int64 (<2^31), every odd 32-bit word of the buffer is 0.
// Reads only the first 8192 int32 words (safe for both layouts).
// ---------------------------------------------------------------------------
__global__ void detect_kernel(const int* __restrict__ sent) {
    int lane = threadIdx.x;
    int acc = 0;
    for (int i = 2 * lane + 1; i < 8192; i += 64) acc |= sent[i];
    #pragma unroll
    for (int off = 16; off; off >>= 1) acc |= __shfl_xor_sync(~0u, acc, off);
    if (lane == 0) g_is64 = (acc == 0) ? 1 : 0;
}

// ---------------------------------------------------------------------------
// Kernel 1: zx[s][b][t] = sum_f<64 emb[tok[s][b]][f] * Win[t][f] + b_in[t] + phi[t]
// One warp per (s,b) row; lane t = (g,q). 4 warps / block.
// ---------------------------------------------------------------------------
__global__ __launch_bounds__(128) void zx_kernel(
    const float* __restrict__ emb, const float* __restrict__ Win,
    const float* __restrict__ b_in, const float* __restrict__ phi,
    const void* __restrict__ sent)
{
    __shared__ float sW[32 * 65];   // Win[t][0..63], padded stride 65 (conflict-free)
    __shared__ float sBP[32];
    int tid = threadIdx.x, lane = tid & 31, wid = tid >> 5;
    for (int i = tid; i < 32 * 64; i += 128) {
        int t = i >> 6, f = i & 63;
        sW[t * 65 + f] = Win[t * 72 + f];
    }
    if (tid < 32) sBP[tid] = b_in[tid] + phi[tid];
    __syncthreads();

    int m = blockIdx.x * 4 + wid;          // m = s*128 + b
    long long tok;
    if (g_is64) tok = ((const long long*)sent)[m];
    else        tok = (long long)(((const int*)sent)[m]);
    const float* x = emb + (size_t)tok * 64;
    float x0 = x[lane];
    float x1 = x[32 + lane];

    float acc = sBP[lane];
    const float* wr = &sW[lane * 65];
    #pragma unroll
    for (int f = 0; f < 32; f++) {
        float xv = __shfl_sync(~0u, x0, f);
        acc = fmaf(xv, wr[f], acc);
    }
    #pragma unroll
    for (int f = 0; f < 32; f++) {
        float xv = __shfl_sync(~0u, x1, f);
        acc = fmaf(xv, wr[32 + f], acc);
    }
    g_zx[m * 32 + lane] = acc;
}

// ---------------------------------------------------------------------------
// Kernel 2: the sequential LSTM scan. One warp per batch b (128 blocks).
// lane t = (g = t>>3, q = t&7).
// ---------------------------------------------------------------------------
__global__ __launch_bounds__(32) void scan_kernel(
    const float* __restrict__ Win, const float* __restrict__ Wout,
    const float* __restrict__ b_out)
{
    int b = blockIdx.x;
    int t = threadIdx.x;
    int g = t >> 3, q = t & 7;

    float wh[8];   // Win[t][64+j] : h-part weights
    float wo[8];   // Wout[g][h=q][j]
    #pragma unroll
    for (int j = 0; j < 8; j++) wh[j] = Win[t * 72 + 64 + j];
    #pragma unroll
    for (int j = 0; j < 8; j++) wo[j] = Wout[t * 8 + j];
    float bo = b_out[t];

    float h = 0.f, c = 0.f;   // valid on lanes 0..7 (h-index = t)

    for (int s = 0; s < S_LEN; s++) {
        float z = g_zx[(s * B_SZ + b) * 32 + t];
        #pragma unroll
        for (int j = 0; j < 8; j++) {
            float hj = __shfl_sync(~0u, h, j);
            z = fmaf(hj, wh[j], z);
        }
        float p = cosf(z);
        // inclusive cumprod within each 8-lane group
        #pragma unroll
        for (int off = 1; off < 8; off <<= 1) {
            float o = __shfl_up_sync(~0u, p, off, 8);
            if (q >= off) p *= o;
        }
        float pre = bo;
        #pragma unroll
        for (int j = 0; j < 8; j++) {
            float qp = __shfl_sync(~0u, p, (g << 3) + j);
            pre = fmaf(qp, wo[j], pre);
        }
        float pf = __shfl_sync(~0u, pre, q);
        float pi = __shfl_sync(~0u, pre, 8 + q);
        float pg = __shfl_sync(~0u, pre, 16 + q);
        float po = __shfl_sync(~0u, pre, 24 + q);
        if (t < 8) {
            float f_ = 1.f / (1.f + expf(-pf));
            float i_ = 1.f / (1.f + expf(-pi));
            float g_ = tanhf(pg);
            float o_ = 1.f / (1.f + expf(-po));
            c = f_ * c + i_ * g_;
            h = o_ * tanhf(c);
            g_h[(s * B_SZ + b) * H_DIM + t] = h;
        }
    }
}

// ---------------------------------------------------------------------------
// Quantum head helpers. State: 256 complex amps per warp; amp index
// idx = lane*8 + r. Wire w <-> bit position p = 7 - w of idx.
// p >= 3 : lane bit (p-3).  p < 3 : register bit p of r.
// All register indices are compile-time (templates / unroll) -> no spills.
// ---------------------------------------------------------------------------
template <int TM>
__device__ __forceinline__ void rot_reg_t(float (&ar)[8], float (&ai)[8],
                                          int type, float c, float s) {
    #pragma unroll
    for (int r = 0; r < 8; r++) {
        if ((r & TM) == 0) {
            const int r1 = r | TM;
            float a0r = ar[r], a0i = ai[r], a1r = ar[r1], a1i = ai[r1];
            if (type == 0) { // RX
                ar[r]  = fmaf(c, a0r,  s * a1i);  ai[r]  = fmaf(c, a0i, -s * a1r);
                ar[r1] = fmaf(c, a1r,  s * a0i);  ai[r1] = fmaf(c, a1i, -s * a0r);
            } else {          // RY (real coefficients)
                ar[r]  = fmaf(c, a0r, -s * a1r);  ai[r]  = fmaf(c, a0i, -s * a1i);
                ar[r1] = fmaf(c, a1r,  s * a0r);  ai[r1] = fmaf(c, a1i,  s * a0i);
            }
        }
    }
}

__device__ __forceinline__ void rot_lane(float (&ar)[8], float (&ai)[8],
                                         int type, int lmask, int lane,
                                         float c, float s) {
    int myb = (lane & lmask) ? 1 : 0;
    #pragma unroll
    for (int r = 0; r < 8; r++) {
        float pr = __shfl_xor_sync(~0u, ar[r], lmask);
        float pi = __shfl_xor_sync(~0u, ai[r], lmask);
        if (type == 0) { // RX: same formula for both sides
            float nr = fmaf(c, ar[r],  s * pi);
            float ni = fmaf(c, ai[r], -s * pr);
            ar[r] = nr; ai[r] = ni;
        } else {          // RY
            float sg = myb ? s : -s;
            ar[r] = fmaf(c, ar[r], sg * pr);
            ai[r] = fmaf(c, ai[r], sg * pi);
        }
    }
}

__device__ __forceinline__ void rz_any(float (&ar)[8], float (&ai)[8],
                                       int p, int lane, float c, float s) {
    #pragma unroll
    for (int r = 0; r < 8; r++) {
        int beta = (p >= 3) ? ((lane >> (p - 3)) & 1) : ((r >> p) & 1);
        float sg = beta ? -s : s;
        float nr = fmaf(c, ar[r],  sg * ai[r]);
        float ni = fmaf(c, ai[r], -sg * ar[r]);
        ar[r] = nr; ai[r] = ni;
    }
}

template <int TM>
__device__ __forceinline__ void cnot_rr_t(float (&ar)[8], float (&ai)[8], int cm) {
    #pragma unroll
    for (int r = 0; r < 8; r++) {
        if (((r & cm) != 0) && ((r & TM) == 0)) {
            const int r1 = r | TM;
            float tr = ar[r]; ar[r] = ar[r1]; ar[r1] = tr;
            float ti = ai[r]; ai[r] = ai[r1]; ai[r1] = ti;
        }
    }
}

template <int TM>
__device__ __forceinline__ void cnot_lr_t(float (&ar)[8], float (&ai)[8], int ctrl) {
    if (ctrl) {
        #pragma unroll
        for (int r = 0; r < 8; r++) {
            if ((r & TM) == 0) {
                const int r1 = r | TM;
                float tr = ar[r]; ar[r] = ar[r1]; ar[r1] = tr;
                float ti = ai[r]; ai[r] = ai[r1]; ai[r1] = ti;
            }
        }
    }
}

__device__ __forceinline__ void cnot_rl(float (&ar)[8], float (&ai)[8],
                                        int cm, int lt) {
    #pragma unroll
    for (int r = 0; r < 8; r++) {
        if (r & cm) {  // warp-uniform condition (r compile-time, cm uniform)
            float sr = __shfl_xor_sync(~0u, ar[r], lt);
            float si = __shfl_xor_sync(~0u, ai[r], lt);
            ar[r] = sr; ai[r] = si;
        }
    }
}

__device__ __forceinline__ void cnot_ll(float (&ar)[8], float (&ai)[8],
                                        int cmask, int lt, int lane) {
    int ctrl = (lane & cmask) != 0;
    #pragma unroll
    for (int r = 0; r < 8; r++) {
        float sr = __shfl_xor_sync(~0u, ar[r], lt);
        float si = __shfl_xor_sync(~0u, ai[r], lt);
        if (ctrl) { ar[r] = sr; ai[r] = si; }
    }
}

__device__ __forceinline__ void apply_op(float (&ar)[8], float (&ai)[8],
                                         int type, int a, int b,
                                         float c, float s, int lane) {
    if (type == 3) {
        int pc_ = 7 - a, pt = 7 - b;
        if (pt < 3) {
            if (pc_ < 3) {
                int cm = 1 << pc_;
                switch (pt) {
                    case 0: cnot_rr_t<1>(ar, ai, cm); break;
                    case 1: cnot_rr_t<2>(ar, ai, cm); break;
                    default: cnot_rr_t<4>(ar, ai, cm); break;
                }
            } else {
                int ctrl = (lane >> (pc_ - 3)) & 1;
                switch (pt) {
                    case 0: cnot_lr_t<1>(ar, ai, ctrl); break;
                    case 1: cnot_lr_t<2>(ar, ai, ctrl); break;
                    default: cnot_lr_t<4>(ar, ai, ctrl); break;
                }
            }
        } else {
            int lt = 1 << (pt - 3);
            if (pc_ < 3) cnot_rl(ar, ai, 1 << pc_, lt);
            else         cnot_ll(ar, ai, 1 << (pc_ - 3), lt, lane);
        }
    } else if (type == 2) {
        rz_any(ar, ai, 7 - a, lane, c, s);
    } else {
        int p = 7 - a;
        if (p < 3) {
            switch (p) {
                case 0: rot_reg_t<1>(ar, ai, type, c, s); break;
                case 1: rot_reg_t<2>(ar, ai, type, c, s); break;
                default: rot_reg_t<4>(ar, ai, type, c, s); break;
            }
        } else {
            rot_lane(ar, ai, type, 1 << (p - 3), lane, c, s);
        }
    }
}

// ---------------------------------------------------------------------------
// Kernel 3: quantum head + log-softmax. One warp per output row n.
// n = s_out*128 + b_out ; source hidden = g_h[(b_out*128 + s_out)*8].
// ---------------------------------------------------------------------------
__global__ __launch_bounds__(128) void head_kernel(
    const float* __restrict__ phiq, const float* __restrict__ Whead,
    const float* __restrict__ b_head, float* __restrict__ out, QOpsParam P)
{
    int warp = (blockIdx.x * blockDim.x + threadIdx.x) >> 5;
    int lane = threadIdx.x & 31;
    int s_out = warp >> 7, b_out = warp & 127;
    const float* hsrc = g_h + ((b_out << 7) + s_out) * H_DIM;

    // RY(theta) encodings fold into a product-state init.
    float myc = 1.f, mys = 0.f;
    if (lane < 8) {
        float th = hsrc[lane] * 0.5f;
        sincosf(th, &mys, &myc);
    }
    float lp = 1.f;
    #pragma unroll
    for (int w = 0; w < 5; w++) {
        float cw = __shfl_sync(~0u, myc, w);
        float sw = __shfl_sync(~0u, mys, w);
        lp *= ((lane >> (4 - w)) & 1) ? sw : cw;
    }
    float c5 = __shfl_sync(~0u, myc, 5), s5 = __shfl_sync(~0u, mys, 5);
    float c6 = __shfl_sync(~0u, myc, 6), s6 = __shfl_sync(~0u, mys, 6);
    float c7 = __shfl_sync(~0u, myc, 7), s7 = __shfl_sync(~0u, mys, 7);

    float ar[8], ai[8];
    #pragma unroll
    for (int r = 0; r < 8; r++) {
        ar[r] = lp * ((r & 4) ? s5 : c5) * ((r & 2) ? s6 : c6) * ((r & 1) ? s7 : c7);
        ai[r] = 0.f;
    }

    // fixed random layer
    for (int o = 0; o < N_OPS; o++) {
        QOp op = P.ops[o];
        apply_op(ar, ai, op.type, op.a, op.b, op.c, op.s, lane);
    }

    // trainable RX(phiq[w]) on every wire
    float pc = 1.f, ps = 0.f;
    if (lane < 8) {
        float th = phiq[lane] * 0.5f;
        sincosf(th, &ps, &pc);
    }
    #pragma unroll
    for (int w = 0; w < 5; w++) {
        float cw = __shfl_sync(~0u, pc, w);
        float sw = __shfl_sync(~0u, ps, w);
        rot_lane(ar, ai, 0, 1 << (4 - w), lane, cw, sw);
    }
    {
        float cw = __shfl_sync(~0u, pc, 5), sw = __shfl_sync(~0u, ps, 5);
        rot_reg_t<4>(ar, ai, 0, cw, sw);
        cw = __shfl_sync(~0u, pc, 6); sw = __shfl_sync(~0u, ps, 6);
        rot_reg_t<2>(ar, ai, 0, cw, sw);
        cw = __shfl_sync(~0u, pc, 7); sw = __shfl_sync(~0u, ps, 7);
        rot_reg_t<1>(ar, ai, 0, cw, sw);
    }

    // measure <Z_w>
    float p[8], tot = 0.f;
    #pragma unroll
    for (int r = 0; r < 8; r++) {
        p[r] = ar[r] * ar[r] + ai[r] * ai[r];
        tot += p[r];
    }
    float z[8];
    #pragma unroll
    for (int w = 0; w < 5; w++) z[w] = ((lane >> (4 - w)) & 1) ? -tot : tot;
    z[5] = (p[0] + p[1] + p[2] + p[3]) - (p[4] + p[5] + p[6] + p[7]);
    z[6] = (p[0] + p[1] + p[4] + p[5]) - (p[2] + p[3] + p[6] + p[7]);
    z[7] = (p[0] + p[2] + p[4] + p[6]) - (p[1] + p[3] + p[5] + p[7]);
    #pragma unroll
    for (int w = 0; w < 8; w++) {
        #pragma unroll
        for (int off = 16; off; off >>= 1)
            z[w] += __shfl_xor_sync(~0u, z[w], off);
    }

    // logits + log-softmax over 12 classes (lanes 0..11, reduce over 16)
    float logit = -1e30f;
    if (lane < 12) {
        logit = b_head[lane];
        #pragma unroll
        for (int k = 0; k < 8; k++) logit = fmaf(z[k], Whead[lane * 8 + k], logit);
    }
    float mx = logit;
    #pragma unroll
    for (int off = 8; off; off >>= 1) mx = fmaxf(mx, __shfl_xor_sync(~0u, mx, off, 16));
    float e = (lane < 12) ? expf(logit - mx) : 0.f;
    float se = e;
    #pragma unroll
    for (int off = 8; off; off >>= 1) se += __shfl_xor_sync(~0u, se, off, 16);
    if (lane < 12) out[warp * T_OUT + lane] = logit - mx - logf(se);
}

// ---------------------------------------------------------------------------
// Host: numpy-legacy MT19937 to regenerate RandomState(1234) random layer.
//  - scalar seed -> init_genrand (mt19937_seed)
//  - randint(n), n <= 2^32 : single 32-bit masked-rejection draw (rk_interval)
//  - uniform : ((a>>5)*2^26 + (b>>6)) / 2^53
// ---------------------------------------------------------------------------
namespace {
struct MTState { uint32_t mt[624]; int mti; };

static void mt_seed(MTState& s, uint32_t seed) {
    s.mt[0] = seed;
    for (int i = 1; i < 624; i++)
        s.mt[i] = 1812433253u * (s.mt[i - 1] ^ (s.mt[i - 1] >> 30)) + (uint32_t)i;
    s.mti = 624;
}
static uint32_t mt_next(MTState& s) {
    if (s.mti >= 624) {
        for (int i = 0; i < 624; i++) {
            uint32_t y = (s.mt[i] & 0x80000000u) | (s.mt[(i + 1) % 624] & 0x7fffffffu);
            s.mt[i] = s.mt[(i + 397) % 624] ^ (y >> 1) ^ ((y & 1u) ? 0x9908b0dfu : 0u);
        }
        s.mti = 0;
    }
    uint32_t y = s.mt[s.mti++];
    y ^= y >> 11;
    y ^= (y << 7) & 0x9d2c5680u;
    y ^= (y << 15) & 0xefc60000u;
    y ^= y >> 18;
    return y;
}
static uint32_t np_randint(MTState& s, uint32_t n) {
    uint32_t rng = n - 1;
    uint32_t mask = rng;
    mask |= mask >> 1; mask |= mask >> 2; mask |= mask >> 4;
    mask |= mask >> 8; mask |= mask >> 16;
    uint32_t v;
    do { v = mt_next(s) & mask; } while (v > rng);
    return v;
}
static double np_double(MTState& s) {
    uint32_t a = mt_next(s) >> 5;
    uint32_t b = mt_next(s) >> 6;
    return ((double)a * 67108864.0 + (double)b) / 9007199254740992.0;
}
static void build_ops(QOpsParam& P) {
    MTState m;
    mt_seed(m, 1234u);
    for (int k = 0; k < N_OPS; k++) {
        uint32_t kind = np_randint(m, 4);
        QOp op;
        if (kind == 3) {
            int c = (int)np_randint(m, 8);
            int t = (int)np_randint(m, 7);
            if (t >= c) t++;
            op.type = 3; op.a = c; op.b = t; op.c = 0.f; op.s = 0.f;
        } else {
            int w = (int)np_randint(m, 8);
            double ang = 6.283185307179586 * np_double(m);
            float th = (float)ang;           // reference casts angle to f32
            float half = 0.5f * th;
            op.type = (int)kind; op.a = w; op.b = 0;
            op.c = cosf(half); op.s = sinf(half);
        }
        P.ops[k] = op;
    }
}
} // namespace

// ---------------------------------------------------------------------------
extern "C" void kernel_launch(void* const* d_in, const int* in_sizes, int n_in,
                              void* d_out, int out_size) {
    (void)in_sizes; (void)n_in; (void)out_size;
    const float* emb    = (const float*)d_in[0];
    const float* Win    = (const float*)d_in[1];
    const float* b_in   = (const float*)d_in[2];
    const float* phi    = (const float*)d_in[3];
    const float* Wout   = (const float*)d_in[4];
    const float* b_out  = (const float*)d_in[5];
    const float* phiq   = (const float*)d_in[6];
    const float* Whead  = (const float*)d_in[7];
    const float* b_head = (const float*)d_in[8];
    const void*  sent   = d_in[9];

    QOpsParam P;
    build_ops(P);

    detect_kernel<<<1, 32>>>((const int*)sent);
    zx_kernel<<<NROWS / 4, 128>>>(emb, Win, b_in, phi, sent);
    scan_kernel<<<B_SZ, 32>>>(Win, Wout, b_out);
    head_kernel<<<NROWS / 4, 128>>>(phiq, Whead, b_head, (float*)d_out, P);
}

// round 2
// speedup vs baseline: 1.3595x; 1.3595x over previous
#include <cuda_runtime.h>
#include <cstdint>
#include <math.h>
#include <complex>

// Problem constants
#define S_LEN 128
#define B_SZ  128
#define H_DIM 8
#define T_OUT 12
#define NROWS (S_LEN * B_SZ)
#define N_RAW 30
#define MAX_EMIT 30

// ---------------------------------------------------------------------------
// Device scratch (no allocations allowed)
// ---------------------------------------------------------------------------
__device__ int   g_is64;
__device__ float g_zx[NROWS * 32];
__device__ float g_h[NROWS * H_DIM];

// op types: 0 = general single-qubit U2, 1 = CNOT, 2 = RZ (diagonal)
struct QOp { int type; int a; int b; float u[8]; };
struct QOpsParam { int n; QOp ops[MAX_EMIT]; };

// ---------------------------------------------------------------------------
// Fast-math helpers (MUFU-based, err ~1e-7; NaN-safe)
// ---------------------------------------------------------------------------
__device__ __forceinline__ float fast_rcp(float x){ float r; asm("rcp.approx.f32 %0,%1;":"=f"(r):"f"(x)); return r; }
__device__ __forceinline__ float fast_ex2(float x){ float r; asm("ex2.approx.f32 %0,%1;":"=f"(r):"f"(x)); return r; }
__device__ __forceinline__ float fast_exp(float x){ return fast_ex2(x * 1.4426950408889634f); }
__device__ __forceinline__ float fast_sigmoid(float x){ return fast_rcp(1.f + fast_exp(-x)); }
__device__ __forceinline__ float fast_tanh(float x){
    x = fminf(fmaxf(x, -9.f), 9.f);
    float e = fast_exp(2.f * x);
    return (e - 1.f) * fast_rcp(e + 1.f);
}

// ---------------------------------------------------------------------------
// Kernel 0: detect int32 vs int64 sentence encoding.
// ---------------------------------------------------------------------------
__global__ void detect_kernel(const int* __restrict__ sent) {
    int lane = threadIdx.x;
    int acc = 0;
    for (int i = 2 * lane + 1; i < 8192; i += 64) acc |= sent[i];
    #pragma unroll
    for (int off = 16; off; off >>= 1) acc |= __shfl_xor_sync(~0u, acc, off);
    if (lane == 0) g_is64 = (acc == 0) ? 1 : 0;
}

// ---------------------------------------------------------------------------
// Kernel 1: zx[s][b][t] = emb[tok]·Win[t][0:64] + b_in[t] + phi[t]
// ---------------------------------------------------------------------------
__global__ __launch_bounds__(128) void zx_kernel(
    const float* __restrict__ emb, const float* __restrict__ Win,
    const float* __restrict__ b_in, const float* __restrict__ phi,
    const void* __restrict__ sent)
{
    __shared__ float sW[32 * 65];
    __shared__ float sBP[32];
    int tid = threadIdx.x, lane = tid & 31, wid = tid >> 5;
    for (int i = tid; i < 32 * 64; i += 128) {
        int t = i >> 6, f = i & 63;
        sW[t * 65 + f] = Win[t * 72 + f];
    }
    if (tid < 32) sBP[tid] = b_in[tid] + phi[tid];
    __syncthreads();

    int m = blockIdx.x * 4 + wid;
    long long tok;
    if (g_is64) tok = ((const long long*)sent)[m];
    else        tok = (long long)(((const int*)sent)[m]);
    const float* x = emb + (size_t)tok * 64;
    float x0 = x[lane];
    float x1 = x[32 + lane];

    float acc = sBP[lane];
    const float* wr = &sW[lane * 65];
    #pragma unroll
    for (int f = 0; f < 32; f++) acc = fmaf(__shfl_sync(~0u, x0, f), wr[f], acc);
    #pragma unroll
    for (int f = 0; f < 32; f++) acc = fmaf(__shfl_sync(~0u, x1, f), wr[32 + f], acc);
    g_zx[m * 32 + lane] = acc;
}

// ---------------------------------------------------------------------------
// Kernel 2: sequential LSTM scan. One warp per batch chain.
// Lane t = (gate g = t>>3, qubit q = t&7). Activations parallel across lanes.
// ---------------------------------------------------------------------------
__global__ __launch_bounds__(32) void scan_kernel(
    const float* __restrict__ Win, const float* __restrict__ Wout,
    const float* __restrict__ b_out)
{
    int b = blockIdx.x;
    int t = threadIdx.x;
    int g = t >> 3, q = t & 7;

    float wh[8], wo[8];
    #pragma unroll
    for (int j = 0; j < 8; j++) wh[j] = Win[t * 72 + 64 + j];
    #pragma unroll
    for (int j = 0; j < 8; j++) wo[j] = Wout[t * 8 + j];
    float bo = b_out[t];

    float h = 0.f, c = 0.f;
    float zn = g_zx[b * 32 + t];     // prefetch s=0

    for (int s = 0; s < S_LEN; s++) {
        float z = zn;
        if (s + 1 < S_LEN) zn = g_zx[((s + 1) * B_SZ + b) * 32 + t]; // hide L2 latency
        #pragma unroll
        for (int j = 0; j < 8; j++)
            z = fmaf(__shfl_sync(~0u, h, j), wh[j], z);
        float p = __cosf(z);
        #pragma unroll
        for (int off = 1; off < 8; off <<= 1) {
            float o = __shfl_up_sync(~0u, p, off, 8);
            if (q >= off) p *= o;
        }
        float pre = bo;
        #pragma unroll
        for (int j = 0; j < 8; j++)
            pre = fmaf(__shfl_sync(~0u, p, (g << 3) + j), wo[j], pre);
        // gate nonlinearities in parallel on all lanes (g==2 -> tanh else sigmoid)
        float act = (g == 2) ? fast_tanh(pre) : fast_sigmoid(pre);
        float af = __shfl_sync(~0u, act, q);
        float ii = __shfl_sync(~0u, act, 8 + q);
        float ag = __shfl_sync(~0u, act, 16 + q);
        float ao = __shfl_sync(~0u, act, 24 + q);
        if (t < 8) {
            c = fmaf(af, c, ii * ag);
            h = ao * fast_tanh(c);
            g_h[(s * B_SZ + b) * H_DIM + t] = h;
        }
    }
}

// ---------------------------------------------------------------------------
// Quantum head. State: 256 amps/warp, idx = lane*8 + r. Wire w <-> bit 7-w.
// bit p >= 3: lane bit (p-3). bit p < 3: register bit p.
// ---------------------------------------------------------------------------
__device__ __forceinline__ void u2_lane(float (&ar)[8], float (&ai)[8],
                                        int lmask, int lane, const float* u) {
    int myb = (lane & lmask) ? 1 : 0;
    float dr = myb ? u[6] : u[0];
    float di = myb ? u[7] : u[1];
    float orr= myb ? u[4] : u[2];
    float oi = myb ? u[5] : u[3];
    #pragma unroll
    for (int r = 0; r < 8; r++) {
        float pr = __shfl_xor_sync(~0u, ar[r], lmask);
        float pi = __shfl_xor_sync(~0u, ai[r], lmask);
        float nr = dr * ar[r] - di * ai[r] + orr * pr - oi * pi;
        float ni = dr * ai[r] + di * ar[r] + orr * pi + oi * pr;
        ar[r] = nr; ai[r] = ni;
    }
}

template <int TM>
__device__ __forceinline__ void u2_reg(float (&ar)[8], float (&ai)[8], const float* u) {
    #pragma unroll
    for (int r = 0; r < 8; r++) {
        if ((r & TM) == 0) {
            const int r1 = r | TM;
            float a0r = ar[r], a0i = ai[r], a1r = ar[r1], a1i = ai[r1];
            ar[r]  = u[0]*a0r - u[1]*a0i + u[2]*a1r - u[3]*a1i;
            ai[r]  = u[0]*a0i + u[1]*a0r + u[2]*a1i + u[3]*a1r;
            ar[r1] = u[4]*a0r - u[5]*a0i + u[6]*a1r - u[7]*a1i;
            ai[r1] = u[4]*a0i + u[5]*a0r + u[6]*a1i + u[7]*a1r;
        }
    }
}

__device__ __forceinline__ void rz_any(float (&ar)[8], float (&ai)[8],
                                       int p, int lane, float c, float s) {
    #pragma unroll
    for (int r = 0; r < 8; r++) {
        int beta = (p >= 3) ? ((lane >> (p - 3)) & 1) : ((r >> p) & 1);
        float sg = beta ? -s : s;
        float nr = fmaf(c, ar[r],  sg * ai[r]);
        float ni = fmaf(c, ai[r], -sg * ar[r]);
        ar[r] = nr; ai[r] = ni;
    }
}

// RX with runtime c,s (for phiq, values only known on device)
template <int TM>
__device__ __forceinline__ void rx_reg(float (&ar)[8], float (&ai)[8], float c, float s) {
    #pragma unroll
    for (int r = 0; r < 8; r++) {
        if ((r & TM) == 0) {
            const int r1 = r | TM;
            float a0r = ar[r], a0i = ai[r], a1r = ar[r1], a1i = ai[r1];
            ar[r]  = fmaf(c, a0r,  s * a1i);  ai[r]  = fmaf(c, a0i, -s * a1r);
            ar[r1] = fmaf(c, a1r,  s * a0i);  ai[r1] = fmaf(c, a1i, -s * a0r);
        }
    }
}

__device__ __forceinline__ void rx_lane(float (&ar)[8], float (&ai)[8],
                                        int lmask, float c, float s) {
    #pragma unroll
    for (int r = 0; r < 8; r++) {
        float pr = __shfl_xor_sync(~0u, ar[r], lmask);
        float pi = __shfl_xor_sync(~0u, ai[r], lmask);
        float nr = fmaf(c, ar[r],  s * pi);
        float ni = fmaf(c, ai[r], -s * pr);
        ar[r] = nr; ai[r] = ni;
    }
}

template <int TM>
__device__ __forceinline__ void cnot_rr_t(float (&ar)[8], float (&ai)[8], int cm) {
    #pragma unroll
    for (int r = 0; r < 8; r++) {
        if (((r & cm) != 0) && ((r & TM) == 0)) {
            const int r1 = r | TM;
            float tr = ar[r]; ar[r] = ar[r1]; ar[r1] = tr;
            float ti = ai[r]; ai[r] = ai[r1]; ai[r1] = ti;
        }
    }
}

template <int TM>
__device__ __forceinline__ void cnot_lr_t(float (&ar)[8], float (&ai)[8], int ctrl) {
    if (ctrl) {
        #pragma unroll
        for (int r = 0; r < 8; r++) {
            if ((r & TM) == 0) {
                const int r1 = r | TM;
                float tr = ar[r]; ar[r] = ar[r1]; ar[r1] = tr;
                float ti = ai[r]; ai[r] = ai[r1]; ai[r1] = ti;
            }
        }
    }
}

__device__ __forceinline__ void cnot_rl(float (&ar)[8], float (&ai)[8], int cm, int lt) {
    #pragma unroll
    for (int r = 0; r < 8; r++) {
        if (r & cm) {
            float sr = __shfl_xor_sync(~0u, ar[r], lt);
            float si = __shfl_xor_sync(~0u, ai[r], lt);
            ar[r] = sr; ai[r] = si;
        }
    }
}

__device__ __forceinline__ void cnot_ll(float (&ar)[8], float (&ai)[8],
                                        int cmask, int lt, int lane) {
    int ctrl = (lane & cmask) != 0;
    #pragma unroll
    for (int r = 0; r < 8; r++) {
        float sr = __shfl_xor_sync(~0u, ar[r], lt);
        float si = __shfl_xor_sync(~0u, ai[r], lt);
        if (ctrl) { ar[r] = sr; ai[r] = si; }
    }
}

// ---------------------------------------------------------------------------
// Kernel 3: quantum head + log-softmax. One warp per output row.
// ---------------------------------------------------------------------------
__global__ __launch_bounds__(128) void head_kernel(
    const float* __restrict__ phiq, const float* __restrict__ Whead,
    const float* __restrict__ b_head, float* __restrict__ out, QOpsParam P)
{
    int warp = (blockIdx.x * blockDim.x + threadIdx.x) >> 5;
    int lane = threadIdx.x & 31;
    int s_out = warp >> 7, b_out = warp & 127;
    const float* hsrc = g_h + ((b_out << 7) + s_out) * H_DIM;

    // RY(h) encodings -> product-state init
    float myc = 1.f, mys = 0.f;
    if (lane < 8) __sincosf(hsrc[lane] * 0.5f, &mys, &myc);
    float lp = 1.f;
    #pragma unroll
    for (int w = 0; w < 5; w++) {
        float cw = __shfl_sync(~0u, myc, w);
        float sw = __shfl_sync(~0u, mys, w);
        lp *= ((lane >> (4 - w)) & 1) ? sw : cw;
    }
    float c5 = __shfl_sync(~0u, myc, 5), s5 = __shfl_sync(~0u, mys, 5);
    float c6 = __shfl_sync(~0u, myc, 6), s6 = __shfl_sync(~0u, mys, 6);
    float c7 = __shfl_sync(~0u, myc, 7), s7 = __shfl_sync(~0u, mys, 7);

    float ar[8], ai[8];
    #pragma unroll
    for (int r = 0; r < 8; r++) {
        ar[r] = lp * ((r & 4) ? s5 : c5) * ((r & 2) ? s6 : c6) * ((r & 1) ? s7 : c7);
        ai[r] = 0.f;
    }

    // fused fixed random layer
    for (int o = 0; o < P.n; o++) {
        const QOp& op = P.ops[o];
        if (op.type == 1) {                 // CNOT
            int pc_ = 7 - op.a, pt = 7 - op.b;
            if (pt < 3) {
                if (pc_ < 3) {
                    int cm = 1 << pc_;
                    switch (pt) {
                        case 0: cnot_rr_t<1>(ar, ai, cm); break;
                        case 1: cnot_rr_t<2>(ar, ai, cm); break;
                        default: cnot_rr_t<4>(ar, ai, cm); break;
                    }
                } else {
                    int ctrl = (lane >> (pc_ - 3)) & 1;
                    switch (pt) {
                        case 0: cnot_lr_t<1>(ar, ai, ctrl); break;
                        case 1: cnot_lr_t<2>(ar, ai, ctrl); break;
                        default: cnot_lr_t<4>(ar, ai, ctrl); break;
                    }
                }
            } else {
                int lt = 1 << (pt - 3);
                if (pc_ < 3) cnot_rl(ar, ai, 1 << pc_, lt);
                else         cnot_ll(ar, ai, 1 << (pc_ - 3), lt, lane);
            }
        } else if (op.type == 2) {          // RZ (possibly fused run of RZs)
            rz_any(ar, ai, 7 - op.a, lane, op.u[0], op.u[1]);
        } else {                             // general U2
            int p = 7 - op.a;
            if (p < 3) {
                switch (p) {
                    case 0: u2_reg<1>(ar, ai, op.u); break;
                    case 1: u2_reg<2>(ar, ai, op.u); break;
                    default: u2_reg<4>(ar, ai, op.u); break;
                }
            } else {
                u2_lane(ar, ai, 1 << (p - 3), lane, op.u);
            }
        }
    }

    // trainable RX(phiq)
    float pc = 1.f, ps = 0.f;
    if (lane < 8) __sincosf(phiq[lane] * 0.5f, &ps, &pc);
    #pragma unroll
    for (int w = 0; w < 5; w++) {
        float cw = __shfl_sync(~0u, pc, w);
        float sw = __shfl_sync(~0u, ps, w);
        rx_lane(ar, ai, 1 << (4 - w), cw, sw);
    }
    {
        float cw = __shfl_sync(~0u, pc, 5), sw = __shfl_sync(~0u, ps, 5);
        rx_reg<4>(ar, ai, cw, sw);
        cw = __shfl_sync(~0u, pc, 6); sw = __shfl_sync(~0u, ps, 6);
        rx_reg<2>(ar, ai, cw, sw);
        cw = __shfl_sync(~0u, pc, 7); sw = __shfl_sync(~0u, ps, 7);
        rx_reg<1>(ar, ai, cw, sw);
    }

    // measure <Z_w>
    float p[8], tot = 0.f;
    #pragma unroll
    for (int r = 0; r < 8; r++) {
        p[r] = ar[r] * ar[r] + ai[r] * ai[r];
        tot += p[r];
    }
    float z[8];
    #pragma unroll
    for (int w = 0; w < 5; w++) z[w] = ((lane >> (4 - w)) & 1) ? -tot : tot;
    z[5] = (p[0] + p[1] + p[2] + p[3]) - (p[4] + p[5] + p[6] + p[7]);
    z[6] = (p[0] + p[1] + p[4] + p[5]) - (p[2] + p[3] + p[6] + p[7]);
    z[7] = (p[0] + p[2] + p[4] + p[6]) - (p[1] + p[3] + p[5] + p[7]);
    #pragma unroll
    for (int w = 0; w < 8; w++) {
        #pragma unroll
        for (int off = 16; off; off >>= 1)
            z[w] += __shfl_xor_sync(~0u, z[w], off);
    }

    // logits + log-softmax (12 classes)
    float logit = -1e30f;
    if (lane < 12) {
        logit = b_head[lane];
        #pragma unroll
        for (int k = 0; k < 8; k++) logit = fmaf(z[k], Whead[lane * 8 + k], logit);
    }
    float mx = logit;
    #pragma unroll
    for (int off = 8; off; off >>= 1) mx = fmaxf(mx, __shfl_xor_sync(~0u, mx, off, 16));
    float e = (lane < 12) ? __expf(logit - mx) : 0.f;
    float se = e;
    #pragma unroll
    for (int off = 8; off; off >>= 1) se += __shfl_xor_sync(~0u, se, off, 16);
    if (lane < 12) out[warp * T_OUT + lane] = logit - mx - __logf(se);
}

// ---------------------------------------------------------------------------
// Host: numpy-legacy MT19937 (RandomState(1234)) + host-side gate fusion.
// ---------------------------------------------------------------------------
namespace {
struct MTState { uint32_t mt[624]; int mti; };

static void mt_seed(MTState& s, uint32_t seed) {
    s.mt[0] = seed;
    for (int i = 1; i < 624; i++)
        s.mt[i] = 1812433253u * (s.mt[i - 1] ^ (s.mt[i - 1] >> 30)) + (uint32_t)i;
    s.mti = 624;
}
static uint32_t mt_next(MTState& s) {
    if (s.mti >= 624) {
        for (int i = 0; i < 624; i++) {
            uint32_t y = (s.mt[i] & 0x80000000u) | (s.mt[(i + 1) % 624] & 0x7fffffffu);
            s.mt[i] = s.mt[(i + 397) % 624] ^ (y >> 1) ^ ((y & 1u) ? 0x9908b0dfu : 0u);
        }
        s.mti = 0;
    }
    uint32_t y = s.mt[s.mti++];
    y ^= y >> 11;
    y ^= (y << 7) & 0x9d2c5680u;
    y ^= (y << 15) & 0xefc60000u;
    y ^= y >> 18;
    return y;
}
static uint32_t np_randint(MTState& s, uint32_t n) {
    uint32_t rng = n - 1;
    uint32_t mask = rng;
    mask |= mask >> 1; mask |= mask >> 2; mask |= mask >> 4;
    mask |= mask >> 8; mask |= mask >> 16;
    uint32_t v;
    do { v = mt_next(s) & mask; } while (v > rng);
    return v;
}
static double np_double(MTState& s) {
    uint32_t a = mt_next(s) >> 5;
    uint32_t b = mt_next(s) >> 6;
    return ((double)a * 67108864.0 + (double)b) / 9007199254740992.0;
}

typedef std::complex<double> cd;

struct Pend {
    cd m[2][2];
    int count;
    bool allrz;
    void reset() { m[0][0] = 1.0; m[0][1] = 0.0; m[1][0] = 0.0; m[1][1] = 1.0; count = 0; allrz = true; }
};

static void build_ops(QOpsParam& P) {
    MTState m;
    mt_seed(m, 1234u);

    Pend pend[8];
    for (int w = 0; w < 8; w++) pend[w].reset();
    P.n = 0;

    auto flush = [&](int w) {
        if (!pend[w].count) return;
        QOp op{};
        if (pend[w].allrz) {
            op.type = 2; op.a = w; op.b = 0;
            op.u[0] = (float)pend[w].m[0][0].real();
            op.u[1] = (float)(-pend[w].m[0][0].imag());
        } else {
            op.type = 0; op.a = w; op.b = 0;
            op.u[0] = (float)pend[w].m[0][0].real(); op.u[1] = (float)pend[w].m[0][0].imag();
            op.u[2] = (float)pend[w].m[0][1].real(); op.u[3] = (float)pend[w].m[0][1].imag();
            op.u[4] = (float)pend[w].m[1][0].real(); op.u[5] = (float)pend[w].m[1][0].imag();
            op.u[6] = (float)pend[w].m[1][1].real(); op.u[7] = (float)pend[w].m[1][1].imag();
        }
        P.ops[P.n++] = op;
        pend[w].reset();
    };

    for (int k = 0; k < N_RAW; k++) {
        uint32_t kind = np_randint(m, 4);
        if (kind == 3) {
            int c = (int)np_randint(m, 8);
            int t = (int)np_randint(m, 7);
            if (t >= c) t++;
            flush(c); flush(t);
            QOp op{}; op.type = 1; op.a = c; op.b = t;
            P.ops[P.n++] = op;
        } else {
            int g = (int)(kind % 3);   // 0=rx,1=ry,2=rz
            int w = (int)np_randint(m, 8);
            double ang = 6.283185307179586 * np_double(m);
            double th = (double)(float)ang;   // reference stores angle as f32
            double c = cos(th * 0.5), s = sin(th * 0.5);
            cd R[2][2];
            if (g == 0) {          // RX
                R[0][0] = c; R[0][1] = cd(0, -s);
                R[1][0] = cd(0, -s); R[1][1] = c;
            } else if (g == 1) {   // RY
                R[0][0] = c; R[0][1] = -s;
                R[1][0] = s; R[1][1] = c;
            } else {               // RZ
                R[0][0] = cd(c, -s); R[0][1] = 0.0;
                R[1][0] = 0.0; R[1][1] = cd(c, s);
            }
            cd n00 = R[0][0] * pend[w].m[0][0] + R[0][1] * pend[w].m[1][0];
            cd n01 = R[0][0] * pend[w].m[0][1] + R[0][1] * pend[w].m[1][1];
            cd n10 = R[1][0] * pend[w].m[0][0] + R[1][1] * pend[w].m[1][0];
            cd n11 = R[1][0] * pend[w].m[0][1] + R[1][1] * pend[w].m[1][1];
            pend[w].m[0][0] = n00; pend[w].m[0][1] = n01;
            pend[w].m[1][0] = n10; pend[w].m[1][1] = n11;
            pend[w].count++;
            if (g != 2) pend[w].allrz = false;
        }
    }
    for (int w = 0; w < 8; w++) flush(w);
}
} // namespace

// ---------------------------------------------------------------------------
extern "C" void kernel_launch(void* const* d_in, const int* in_sizes, int n_in,
                              void* d_out, int out_size) {
    (void)in_sizes; (void)n_in; (void)out_size;
    const float* emb    = (const float*)d_in[0];
    const float* Win    = (const float*)d_in[1];
    const float* b_in   = (const float*)d_in[2];
    const float* phi    = (const float*)d_in[3];
    const float* Wout   = (const float*)d_in[4];
    const float* b_out  = (const float*)d_in[5];
    const float* phiq   = (const float*)d_in[6];
    const float* Whead  = (const float*)d_in[7];
    const float* b_head = (const float*)d_in[8];
    const void*  sent   = d_in[9];

    QOpsParam P;
    build_ops(P);

    detect_kernel<<<1, 32>>>((const int*)sent);
    zx_kernel<<<NROWS / 4, 128>>>(emb, Win, b_in, phi, sent);
    scan_kernel<<<B_SZ, 32>>>(Win, Wout, b_out);
    head_kernel<<<NROWS / 4, 128>>>(phiq, Whead, b_head, (float*)d_out, P);
}